// round 11
// baseline (speedup 1.0000x reference)
#include <cuda_runtime.h>
#include <cuda_fp16.h>
#include <float.h>
#include <cstdint>

#define B_   8
#define C_   64
#define N_   4096
#define K_   20
#define M_   8
#define OUTC 64
#define CM   512          // C_*M_
#define PTS  (B_*N_)      // 32768

// Scratch (allocation-free rule: __device__ globals)
__device__ __align__(16) __half g_ftH[B_*N_*C_];           // feature fp16 [b][n][c] (4 MB)
__device__ __align__(16) __half g_aggH[(size_t)PTS*CM];    // agg fp16 [pt][jperm]  (32 MB)
__device__ __align__(16) __half g_wh[CM*OUTC];             // conv_w fp16 [oc][jperm]
__device__ __align__(16) float4 g_x4[PTS];                 // packed coords         (512 KB)

__device__ __forceinline__ uint32_t smem_u32(const void* p) {
    uint32_t a;
    asm("{ .reg .u64 t; cvta.to.shared.u64 t, %1; cvt.u32.u64 %0, t; }" : "=r"(a) : "l"(p));
    return a;
}
__device__ __forceinline__ void ffma2(unsigned long long& d,
                                      unsigned long long a, unsigned long long b) {
    asm("fma.rn.f32x2 %0, %1, %2, %0;" : "+l"(d) : "l"(a), "l"(b));
}
__device__ __forceinline__ unsigned long long pack2(float x, float y) {
    unsigned long long r;
    asm("mov.b64 %0, {%1, %2};" : "=l"(r) : "f"(x), "f"(y));
    return r;
}
__device__ __forceinline__ float2 unpack2(unsigned long long v) {
    float2 f;
    asm("mov.b64 {%0, %1}, %2;" : "=f"(f.x), "=f"(f.y) : "l"(v));
    return f;
}

// ===========================================================================
// K1: feature (B,C,N) fp32 -> g_ftH (B,N,C) fp16; both sides 128B-coalesced
// ===========================================================================
__global__ void k_transpose_feat(const float* __restrict__ feat) {
    __shared__ float tile[32][66];                 // [n][c], +2 pad
    const int b  = blockIdx.z;
    const int n0 = blockIdx.x * 32;
    const int tx = threadIdx.x, ty = threadIdx.y;  // block (32,8)
    const float* fb = feat + (size_t)b * C_ * N_;
    #pragma unroll
    for (int cc = 0; cc < 8; cc++) {
        const int c = cc * 8 + ty;
        tile[tx][c] = fb[(size_t)c * N_ + n0 + tx];
    }
    __syncthreads();
    __half* ob = g_ftH + (size_t)b * N_ * C_;
    #pragma unroll
    for (int r = 0; r < 4; r++) {
        const int n = r * 8 + ty;
        const float2 v = *(const float2*)&tile[n][2 * tx];
        *(__half2*)(ob + (size_t)(n0 + n) * C_ + 2 * tx) =
            __floats2half2_rn(v.x, v.y);
    }
}

// ===========================================================================
// Prep: conv_w -> fp16 with the SAME j-permutation K3 uses for its stores,
//       plus x -> packed float4 per point. (GEMM contracts over j: applying
//       one fixed permutation to BOTH operands is exact.)
//       perm: pos in [0,256):  j = 16*(pos>>3)      + (pos&7)
//             pos in [256,512): j = 16*((pos-256)>>3) + (pos&7) + 8
// ===========================================================================
__global__ void k_prep(const float* __restrict__ w, const float* __restrict__ x) {
    const int i = blockIdx.x * blockDim.x + threadIdx.x;   // 0 .. 32767
    const int oc  = i >> 9;
    const int pos = i & 511;
    const int l   = (pos >> 3) & 31;
    const int jj  = 16 * l + (pos & 7) + ((pos >> 8) << 3);
    g_wh[i] = __float2half(w[(oc << 9) + jj]);

    const int b = i >> 12;
    const int n = i & (N_ - 1);
    const float* xb = x + (size_t)b * 3 * N_;
    g_x4[i] = make_float4(xb[n], xb[N_ + n], xb[2*N_ + n], 0.f);
}

// ===========================================================================
// K3: warp-per-point: perm matrix + softmax + aggregation -> g_aggH[pt][jperm]
//     shuffle-broadcast indices, fully coalesced permuted stores
// ===========================================================================
__global__ void __launch_bounds__(256) k_agg(
    const int*   __restrict__ nidx,          // int32 (JAX x64 disabled)
    const float* __restrict__ kern)
{
    const int warp = threadIdx.x >> 5;
    const int lane = threadIdx.x & 31;
    const int pt   = blockIdx.x * 8 + warp;
    const int b    = pt >> 12;

    __shared__ float p_s[8][20][8];

    float px[8];
    int ik = 0;
    float x0 = 0.f, x1 = 0.f, x2 = 0.f;
    if (lane < K_) {
        ik = nidx[pt * K_ + lane] & (N_ - 1);
        const float4 xv = g_x4[(b << 12) + ik];
        x0 = xv.x; x1 = xv.y; x2 = xv.z;
    }
    const float r0 = x0 - __shfl_sync(0xFFFFFFFFu, x0, 0);
    const float r1 = x1 - __shfl_sync(0xFFFFFFFFu, x1, 0);
    const float r2 = x2 - __shfl_sync(0xFFFFFFFFu, x2, 0);

    #pragma unroll
    for (int m = 0; m < M_; m++) {
        float v = r0 * kern[m] + r1 * kern[M_ + m] + r2 * kern[2*M_ + m];
        if (lane == 0 && m == 0) v += 1.0f;       // one_pad
        px[m] = v;
    }

    // softmax over k (no max-shift; logits are small, fp32 exp safe)
    #pragma unroll
    for (int m = 0; m < M_; m++) {
        const float e = (lane < K_) ? __expf(px[m]) : 0.f;
        float s = e;
        #pragma unroll
        for (int o = 16; o > 0; o >>= 1)
            s += __shfl_xor_sync(0xFFFFFFFFu, s, o);
        px[m] = e * (1.0f / s);
    }
    if (lane < K_) {
        float4* dst = (float4*)p_s[warp][lane];
        dst[0] = make_float4(px[0], px[1], px[2], px[3]);
        dst[1] = make_float4(px[4], px[5], px[6], px[7]);
    }
    __syncwarp();

    // ---- batched feature gather (indices via warp shuffle broadcast) ----
    const int c0 = lane * 2;
    const __half* ftb = g_ftH + ((size_t)b << 12) * C_;
    uint32_t f[20];
    #pragma unroll
    for (int k = 0; k < K_; k++) {
        const int ii = __shfl_sync(0xFFFFFFFFu, ik, k);
        f[k] = *(const uint32_t*)(ftb + (size_t)ii * C_ + c0);
    }

    unsigned long long accA[4] = {0,0,0,0};   // channel c0
    unsigned long long accB[4] = {0,0,0,0};   // channel c0+1
    union f4u { float4 v; unsigned long long u[2]; };

    #pragma unroll
    for (int k = 0; k < K_; k++) {
        const float2 fc = __half22float2(*(__half2*)&f[k]);
        const unsigned long long fxx = pack2(fc.x, fc.x);
        const unsigned long long fyy = pack2(fc.y, fc.y);
        f4u pa, pb;
        pa.v = *((const float4*)p_s[warp][k]);
        pb.v = *((const float4*)p_s[warp][k] + 1);
        ffma2(accA[0], fxx, pa.u[0]);  ffma2(accA[1], fxx, pa.u[1]);
        ffma2(accA[2], fxx, pb.u[0]);  ffma2(accA[3], fxx, pb.u[1]);
        ffma2(accB[0], fyy, pa.u[0]);  ffma2(accB[1], fyy, pa.u[1]);
        ffma2(accB[2], fyy, pb.u[0]);  ffma2(accB[3], fyy, pb.u[1]);
    }

    // fp16 pack + permuted coalesced store:
    //   h0 (j=16l..16l+7)  -> pos 8l..8l+7      (bytes [16l,16l+16) of 512B half-row)
    //   h1 (j=16l+8..+15)  -> pos 256+8l..+7
    __half2 h[8];
    #pragma unroll
    for (int i = 0; i < 4; i++) {
        const float2 fa = unpack2(accA[i]);
        const float2 fb = unpack2(accB[i]);
        h[i]     = __floats2half2_rn(fa.x, fa.y);
        h[4 + i] = __floats2half2_rn(fb.x, fb.y);
    }
    __half* dst = g_aggH + (size_t)pt * CM;
    *(uint4*)(dst + 8 * lane)       = *(uint4*)(h);
    *(uint4*)(dst + 256 + 8 * lane) = *(uint4*)(h + 4);
}

// ===========================================================================
// K4: HMMA fp16 GEMM, 64pt x 64oc tiles, 4-stage cp.async pipeline
// ===========================================================================
#define AS_STRIDE 72
#define BS_STRIDE 72
#define OS_STRIDE 68
#define STAGE_HALVES (64 * AS_STRIDE + 64 * BS_STRIDE)      // 9216 halves
#define SMEM_K4 (4 * STAGE_HALVES * 2)                      // 73728 B

__global__ void __launch_bounds__(256) k_gemm_hmma(
    const float* __restrict__ bias,
    const float* __restrict__ feat,
    float* __restrict__ out)
{
    extern __shared__ __half smemh[];

    const int tid  = threadIdx.x;
    const int wid  = tid >> 5;
    const int lane = tid & 31;
    const int warp_m = (wid & 3) * 16;   // 4 warps over 64 pts
    const int warp_n = (wid >> 2) * 32;  // 2 warps over 64 ocs
    const int ptBase = blockIdx.x * 64;

    float acc[4][4];
    #pragma unroll
    for (int ni = 0; ni < 4; ni++)
        #pragma unroll
        for (int r = 0; r < 4; r++) acc[ni][r] = 0.f;

    const __half* aSrc = g_aggH + (size_t)ptBase * CM;

    auto load_chunk = [&](int s, int kc) {
        __half* sa = smemh + s * STAGE_HALVES;
        __half* sb = sa + 64 * AS_STRIDE;
        #pragma unroll
        for (int i = 0; i < 2; i++) {
            const int c   = tid + i * 256;
            const int row = c >> 3;
            const int c8  = c & 7;
            asm volatile("cp.async.cg.shared.global [%0], [%1], 16;" ::
                "r"(smem_u32(sa + row * AS_STRIDE + c8 * 8)),
                "l"(aSrc + (size_t)row * CM + kc + c8 * 8));
        }
        #pragma unroll
        for (int i = 0; i < 2; i++) {
            const int c   = tid + i * 256;
            const int row = c >> 3;
            const int c8  = c & 7;
            asm volatile("cp.async.cg.shared.global [%0], [%1], 16;" ::
                "r"(smem_u32(sb + row * BS_STRIDE + c8 * 8)),
                "l"(g_wh + (size_t)row * CM + kc + c8 * 8));
        }
    };

    // prologue: 3 stages in flight
    #pragma unroll
    for (int s = 0; s < 3; s++) {
        load_chunk(s, s * 64);
        asm volatile("cp.async.commit_group;");
    }

    for (int kc8 = 0; kc8 < 8; kc8++) {
        if (kc8 < 5) {
            load_chunk((kc8 + 3) & 3, (kc8 + 3) * 64);
            asm volatile("cp.async.commit_group;");
            asm volatile("cp.async.wait_group 3;");
        } else if (kc8 == 5) {
            asm volatile("cp.async.wait_group 2;");
        } else if (kc8 == 6) {
            asm volatile("cp.async.wait_group 1;");
        } else {
            asm volatile("cp.async.wait_group 0;");
        }
        __syncthreads();

        const __half* sa = smemh + (kc8 & 3) * STAGE_HALVES;
        const __half* sb = sa + 64 * AS_STRIDE;
        #pragma unroll
        for (int ks = 0; ks < 4; ks++) {
            uint32_t a[4];
            {
                const uint32_t addr = smem_u32(
                    sa + (warp_m + (lane & 15)) * AS_STRIDE
                       + ks * 16 + (lane >> 4) * 8);
                asm volatile("ldmatrix.sync.aligned.m8n8.x4.shared.b16 "
                             "{%0,%1,%2,%3}, [%4];"
                             : "=r"(a[0]), "=r"(a[1]), "=r"(a[2]), "=r"(a[3])
                             : "r"(addr));
            }
            uint32_t bfr[4][2];
            #pragma unroll
            for (int ni = 0; ni < 4; ni++) {
                const uint32_t addr = smem_u32(
                    sb + (warp_n + ni * 8 + (lane & 7)) * BS_STRIDE
                       + ks * 16 + ((lane >> 3) & 1) * 8);
                asm volatile("ldmatrix.sync.aligned.m8n8.x2.shared.b16 "
                             "{%0,%1}, [%2];"
                             : "=r"(bfr[ni][0]), "=r"(bfr[ni][1])
                             : "r"(addr));
            }
            #pragma unroll
            for (int ni = 0; ni < 4; ni++) {
                asm volatile(
                    "mma.sync.aligned.m16n8k16.row.col.f32.f16.f16.f32 "
                    "{%0,%1,%2,%3}, {%4,%5,%6,%7}, {%8,%9}, {%0,%1,%2,%3};"
                    : "+f"(acc[ni][0]), "+f"(acc[ni][1]),
                      "+f"(acc[ni][2]), "+f"(acc[ni][3])
                    : "r"(a[0]), "r"(a[1]), "r"(a[2]), "r"(a[3]),
                      "r"(bfr[ni][0]), "r"(bfr[ni][1]));
            }
        }
        __syncthreads();
    }

    // scatter fragments to smem as [oc][pt] (overlays stage 0; all loads done)
    float* osm = (float*)smemh;
    {
        const int r  = lane >> 2;
        const int cp = (lane & 3) * 2;
        #pragma unroll
        for (int ni = 0; ni < 4; ni++) {
            const int pt0 = warp_m + r;
            const int oc0 = warp_n + ni * 8 + cp;
            osm[oc0 * OS_STRIDE + pt0]           = acc[ni][0];
            osm[(oc0 + 1) * OS_STRIDE + pt0]     = acc[ni][1];
            osm[oc0 * OS_STRIDE + pt0 + 8]       = acc[ni][2];
            osm[(oc0 + 1) * OS_STRIDE + pt0 + 8] = acc[ni][3];
        }
    }
    __syncthreads();

    // fused epilogue: bias + leaky_relu + residual
    const int b  = ptBase >> 12;
    const int n0 = ptBase & (N_ - 1);
    #pragma unroll
    for (int i = 0; i < 4; i++) {
        const int c    = tid + i * 256;    // 1024 float4 tasks
        const int oc   = c >> 4;
        const int col4 = (c & 15) * 4;
        const float* src = osm + oc * OS_STRIDE + col4;
        const size_t o = ((size_t)(b * OUTC + oc)) * N_ + n0 + col4;
        const float4 f = *(const float4*)(feat + o);
        const float bb = bias[oc];
        float4 v;
        v.x = src[0] + bb; v.x = (v.x > 0.f ? v.x : 0.2f * v.x) + f.x;
        v.y = src[1] + bb; v.y = (v.y > 0.f ? v.y : 0.2f * v.y) + f.y;
        v.z = src[2] + bb; v.z = (v.z > 0.f ? v.z : 0.2f * v.z) + f.z;
        v.w = src[3] + bb; v.w = (v.w > 0.f ? v.w : 0.2f * v.w) + f.w;
        *(float4*)(out + o) = v;
    }
}

// ===========================================================================
extern "C" void kernel_launch(void* const* d_in, const int* in_sizes, int n_in,
                              void* d_out, int out_size) {
    const float* x    = (const float*)d_in[0];
    const float* feat = (const float*)d_in[1];
    const int*   nidx = (const int*)d_in[2];     // int32: JAX x64 is disabled
    const float* kern = (const float*)d_in[3];
    const float* w    = (const float*)d_in[4];
    const float* bias = (const float*)d_in[5];
    float* out = (float*)d_out;

    cudaFuncSetAttribute(k_gemm_hmma, cudaFuncAttributeMaxDynamicSharedMemorySize, SMEM_K4);

    k_transpose_feat<<<dim3(N_/32, 1, B_), dim3(32, 8)>>>(feat);
    k_prep<<<PTS/256, 256>>>(w, x);
    k_agg<<<PTS/8, 256>>>(nidx, kern);
    k_gemm_hmma<<<PTS/64, 256, SMEM_K4>>>(bias, feat, out);
}